// round 12
// baseline (speedup 1.0000x reference)
#include <cuda_runtime.h>
#include <math.h>

#define TSTEPS 64
#define BATCH  32
#define NH     512
#define NH2    1024
#define VOCAB  32000
#define RROWS  (TSTEPS*BATCH)   // 2048
#define NBLK   256

// ---------------------------------------------------------------------------
// Scratch (static device globals; no allocation anywhere)
// ---------------------------------------------------------------------------
__device__ __align__(16) float g_X[RROWS*NH];
__device__ __align__(16) float g_Xpre[RROWS*NH2];
__device__ __align__(16) float g_states[8][BATCH*NH];
__device__ __align__(16) float g_h[BATCH*NH];
__device__ __align__(16) float g_hid[RROWS*NH];
__device__ __align__(16) float g_logits[(size_t)RROWS*VOCAB];
__device__ __align__(16) float g_W0hT[NH2*NH];              // W0[512:,:]^T  [n][k]
__device__ __align__(16) float g_WsT[64*NH2*NH];            // Ws[i][j]^T    [n][k] (slot i*8+j)
__device__ unsigned g_barCount = 0;
__device__ unsigned g_barGen   = 0;

__device__ __forceinline__ float sigm(float x) { return 1.f / (1.f + expf(-x)); }

// ---------------------------------------------------------------------------
// Grid-wide barrier (sense-reversing); all NBLK blocks guaranteed co-resident.
// ---------------------------------------------------------------------------
__device__ __forceinline__ void gsync() {
    __syncthreads();
    if (threadIdx.x == 0) {
        __threadfence();
        unsigned gen = *(volatile unsigned*)&g_barGen;
        if (atomicAdd(&g_barCount, 1u) == NBLK - 1) {
            atomicExch(&g_barCount, 0u);
            __threadfence();
            atomicAdd(&g_barGen, 1u);
        } else {
            while (*(volatile unsigned*)&g_barGen == gen) { __nanosleep(32); }
        }
        __threadfence();
    }
    __syncthreads();
}

// ---------------------------------------------------------------------------
// Setup kernels
// ---------------------------------------------------------------------------
__global__ __launch_bounds__(256) void kInitH(const float* __restrict__ h0) {
    int idx = blockIdx.x * 256 + threadIdx.x;
    if (idx < BATCH*NH) g_h[idx] = h0[idx];
}

__global__ __launch_bounds__(128) void kEmbed(const int* __restrict__ ids,
                                              const float* __restrict__ emb) {
    int r = blockIdx.x;
    int row = ids[r];
    const float4* src = reinterpret_cast<const float4*>(emb + (size_t)row * NH);
    float4* dst = reinterpret_cast<float4*>(g_X + (size_t)r * NH);
    dst[threadIdx.x] = src[threadIdx.x];
}

// Xpre = g_X[2048,512] @ W0[0:512, 0:1024]
__global__ __launch_bounds__(256) void kXpreGemm(const float* __restrict__ W0) {
    __shared__ __align__(16) float As[16][64];
    __shared__ __align__(16) float Bs[16][64];
    const int m0 = blockIdx.y * 64, n0 = blockIdx.x * 64;
    const int tid = threadIdx.x, tx = tid & 15, ty = tid >> 4;
    const int am = tid >> 2, ak4 = (tid & 3) * 4;
    const int bk = tid >> 4, bn4 = (tid & 15) * 4;
    float acc[4][4];
#pragma unroll
    for (int i = 0; i < 4; i++)
#pragma unroll
        for (int j = 0; j < 4; j++) acc[i][j] = 0.f;
    for (int k0 = 0; k0 < NH; k0 += 16) {
        float4 av = *reinterpret_cast<const float4*>(g_X + (size_t)(m0+am)*NH + k0 + ak4);
        As[ak4+0][am] = av.x; As[ak4+1][am] = av.y; As[ak4+2][am] = av.z; As[ak4+3][am] = av.w;
        *reinterpret_cast<float4*>(&Bs[bk][bn4]) =
            *reinterpret_cast<const float4*>(W0 + (size_t)(k0+bk)*NH2 + n0 + bn4);
        __syncthreads();
#pragma unroll
        for (int kk = 0; kk < 16; kk++) {
            float4 a = *reinterpret_cast<float4*>(&As[kk][ty*4]);
            float4 b = *reinterpret_cast<float4*>(&Bs[kk][tx*4]);
            float aa[4] = {a.x,a.y,a.z,a.w}, bb[4] = {b.x,b.y,b.z,b.w};
#pragma unroll
            for (int i = 0; i < 4; i++)
#pragma unroll
                for (int j = 0; j < 4; j++) acc[i][j] += aa[i]*bb[j];
        }
        __syncthreads();
    }
#pragma unroll
    for (int i = 0; i < 4; i++) {
        float4 st = make_float4(acc[i][0], acc[i][1], acc[i][2], acc[i][3]);
        *reinterpret_cast<float4*>(g_Xpre + (size_t)(m0+ty*4+i)*NH2 + n0 + tx*4) = st;
    }
}

// Transpose all 28 used Ws[i][j] plus W0[512:,:] into [n][k] layouts.
// z=0..27 -> edge (i,j); z=28 -> W0h.
__global__ __launch_bounds__(256) void kTransAll(const float* __restrict__ W0,
                                                 const float* __restrict__ Ws) {
    const int z = blockIdx.z;
    const float* src; float* dst;
    if (z == 28) { src = W0 + (size_t)NH * NH2; dst = g_W0hT; }
    else {
        int i = 0, rem = z;
        while (rem >= 7 - i) { rem -= 7 - i; i++; }
        int j = i + 1 + rem;
        src = Ws + (size_t)(i*8 + j) * NH * NH2;
        dst = g_WsT + (size_t)(i*8 + j) * NH * NH2;
    }
    __shared__ float tile[32][33];
    const int nb = blockIdx.x << 5, kb = blockIdx.y << 5;
    const int tx = threadIdx.x & 31, ty4 = (threadIdx.x >> 5) << 2;
#pragma unroll
    for (int r = 0; r < 4; r++)
        tile[ty4 + r][tx] = src[(size_t)(kb + ty4 + r) * NH2 + nb + tx];
    __syncthreads();
#pragma unroll
    for (int r = 0; r < 4; r++)
        dst[(size_t)(nb + ty4 + r) * NH + kb + tx] = tile[tx][ty4 + r];
}

// ---------------------------------------------------------------------------
// Per-unit GEMM core: 8 warps x 1 paired col, lanes = 32 batch rows, K=512.
// State staged to smem [k][b]; weights streamed from [n][k] layout via L1/L2.
// ---------------------------------------------------------------------------
__device__ __forceinline__ void unit_gemm(const float* __restrict__ S,
                                          const float* __restrict__ Wcol,
                                          float (*As)[33],
                                          float& accC, float& accH) {
    const int tid = threadIdx.x, lane = tid & 31;
    const int sb = tid >> 3, sk = (tid & 7) << 3;
    accC = 0.f; accH = 0.f;
    const float4* wc4 = reinterpret_cast<const float4*>(Wcol);
    const float4* wh4 = reinterpret_cast<const float4*>(Wcol + (1 << 18)); // +512*512
    for (int k0 = 0; k0 < NH; k0 += 64) {
        const float4* sp = reinterpret_cast<const float4*>(S + sb * NH + k0 + sk);
        float4 v0 = __ldcg(sp), v1 = __ldcg(sp + 1);
        As[sk+0][sb]=v0.x; As[sk+1][sb]=v0.y; As[sk+2][sb]=v0.z; As[sk+3][sb]=v0.w;
        As[sk+4][sb]=v1.x; As[sk+5][sb]=v1.y; As[sk+6][sb]=v1.z; As[sk+7][sb]=v1.w;
        __syncthreads();
        const float4* wcp = wc4 + (k0 >> 2);
        const float4* whp = wh4 + (k0 >> 2);
#pragma unroll 8
        for (int q = 0; q < 16; q++) {
            float4 wc = __ldg(wcp + q);
            float4 wh = __ldg(whp + q);
            float s0 = As[q*4+0][lane], s1 = As[q*4+1][lane];
            float s2 = As[q*4+2][lane], s3 = As[q*4+3][lane];
            accC = fmaf(s0, wc.x, accC); accH = fmaf(s0, wh.x, accH);
            accC = fmaf(s1, wc.y, accC); accH = fmaf(s1, wh.y, accH);
            accC = fmaf(s2, wc.z, accC); accH = fmaf(s2, wh.z, accH);
            accC = fmaf(s3, wc.w, accC); accH = fmaf(s3, wh.w, accH);
        }
        __syncthreads();
    }
}

// ---------------------------------------------------------------------------
// Persistent recurrence: all 64 steps in one launch, grid barriers between
// DAG stages. 9 barriers/step.
// ---------------------------------------------------------------------------
__global__ __launch_bounds__(NBLK >= 256 ? 256 : 256, 2) void kRecur(float* __restrict__ lastOut) {
    __shared__ __align__(16) float As[64][33];
    const int tid = threadIdx.x, lane = tid & 31, warp = tid >> 5;

    for (int t = 0; t < TSTEPS; t++) {
        // ---- node0: s0 = h + sig(c0)*(tanh(h0c) - h), [c0|h0c] = Xpre[t] + h@W0h
        for (int u = blockIdx.x; u < 64; u += NBLK) {
            const int d = ((u & 63) << 3) + warp;          // paired col 0..511
            float accC, accH;
            unit_gemm(g_h, g_W0hT + (size_t)d * NH, As, accC, accH);
            const float* xp = g_Xpre + ((size_t)(t * BATCH) << 10);
            float cc = accC + __ldg(xp + (lane << 10) + d);
            float hh = accH + __ldg(xp + (lane << 10) + NH + d);
            float hp = __ldcg(g_h + lane * NH + d);
            float s0 = hp + sigm(cc) * (tanhf(hh) - hp);
            __stcg(g_states[0] + lane * NH + d, s0);
        }
        gsync();

        // ---- edge stages i = 0..6
        for (int i = 0; i < 7; i++) {
            const int units = (7 - i) << 6;
            const float inv = (i == 0) ? 1.f : 1.f / (float)i;
            const float* Sst = g_states[i];
            for (int u = blockIdx.x; u < units; u += NBLK) {
                const int e = u >> 6;
                const int j = i + 1 + e;
                const int d = ((u & 63) << 3) + warp;
                const float* slot = g_WsT + (size_t)(i*8 + j) * NH * NH2;
                float accC, accH;
                unit_gemm(Sst, slot + (size_t)d * NH, As, accC, accH);
                float sp = __ldcg(Sst + lane * NH + d) * inv;
                float cc = accC * inv, hh = accH * inv;
                float act;
                if (j == 1 || j == 4)      act = tanhf(hh);
                else if (j == 2 || j == 5) act = fmaxf(hh, 0.f);
                else if (j == 3 || j == 6) act = sigm(hh);
                else                       act = hh;       // j == 7 identity
                float s = sp + sigm(cc) * (act - sp);
                float* dst = g_states[j] + lane * NH + d;
                if (i == 0) __stcg(dst, s);
                else        __stcg(dst, __ldcg(dst) + s);
            }
            gsync();
        }

        // ---- avg: h = mean_{j=1..7} states[j]/j ; write g_h, g_hid[t], last_h
        {
            if (tid < 64) {
                int idx = blockIdx.x * 64 + tid;           // 256*64 = 16384
                float s = 0.f;
#pragma unroll
                for (int j = 1; j < 8; j++)
                    s += __ldcg(g_states[j] + idx) * (1.f / (float)j);
                s *= (1.f / 7.f);
                __stcg(g_h + idx, s);
                g_hid[(size_t)t * BATCH * NH + idx] = s;
                if (t == TSTEPS - 1) lastOut[idx] = s;
            }
            gsync();
        }
    }
}

// ---------------------------------------------------------------------------
// Decoder: logits[r,v] = g_hid[r,:] . emb[v,:] + bias[v]
// 128x128 tile, 8x8 micro, 256 threads.
// ---------------------------------------------------------------------------
__global__ __launch_bounds__(256) void kDec2(const float* __restrict__ emb,
                                             const float* __restrict__ bias) {
    __shared__ __align__(16) float As[16][132];
    __shared__ __align__(16) float Bs[16][132];
    const int m0 = blockIdx.y << 7, n0 = blockIdx.x << 7;
    const int tid = threadIdx.x;
    const int tx = tid & 15, ty = tid >> 4;
    const int lr = tid >> 1, lk = (tid & 1) << 3;
    float acc[8][8];
#pragma unroll
    for (int i = 0; i < 8; i++)
#pragma unroll
        for (int j = 0; j < 8; j++) acc[i][j] = 0.f;
    const float* Ap = g_hid + (size_t)(m0 + lr) * NH + lk;
    const float* Bp = emb   + (size_t)(n0 + lr) * NH + lk;

    for (int k0 = 0; k0 < NH; k0 += 16) {
        float4 a0 = __ldg(reinterpret_cast<const float4*>(Ap + k0));
        float4 a1 = __ldg(reinterpret_cast<const float4*>(Ap + k0 + 4));
        float4 b0 = __ldg(reinterpret_cast<const float4*>(Bp + k0));
        float4 b1 = __ldg(reinterpret_cast<const float4*>(Bp + k0 + 4));
        As[lk+0][lr]=a0.x; As[lk+1][lr]=a0.y; As[lk+2][lr]=a0.z; As[lk+3][lr]=a0.w;
        As[lk+4][lr]=a1.x; As[lk+5][lr]=a1.y; As[lk+6][lr]=a1.z; As[lk+7][lr]=a1.w;
        Bs[lk+0][lr]=b0.x; Bs[lk+1][lr]=b0.y; Bs[lk+2][lr]=b0.z; Bs[lk+3][lr]=b0.w;
        Bs[lk+4][lr]=b1.x; Bs[lk+5][lr]=b1.y; Bs[lk+6][lr]=b1.z; Bs[lk+7][lr]=b1.w;
        __syncthreads();
#pragma unroll
        for (int kk = 0; kk < 16; kk++) {
            float4 t0 = *reinterpret_cast<const float4*>(&As[kk][ty<<3]);
            float4 t1 = *reinterpret_cast<const float4*>(&As[kk][(ty<<3)+4]);
            float4 u0 = *reinterpret_cast<const float4*>(&Bs[kk][tx<<3]);
            float4 u1 = *reinterpret_cast<const float4*>(&Bs[kk][(tx<<3)+4]);
            float a[8] = {t0.x,t0.y,t0.z,t0.w,t1.x,t1.y,t1.z,t1.w};
            float b[8] = {u0.x,u0.y,u0.z,u0.w,u1.x,u1.y,u1.z,u1.w};
#pragma unroll
            for (int i = 0; i < 8; i++)
#pragma unroll
                for (int j = 0; j < 8; j++) acc[i][j] = fmaf(a[i], b[j], acc[i][j]);
        }
        __syncthreads();
    }
    float4 bz0 = __ldg(reinterpret_cast<const float4*>(bias + n0 + (tx<<3)));
    float4 bz1 = __ldg(reinterpret_cast<const float4*>(bias + n0 + (tx<<3) + 4));
    float bb[8] = {bz0.x,bz0.y,bz0.z,bz0.w,bz1.x,bz1.y,bz1.z,bz1.w};
#pragma unroll
    for (int i = 0; i < 8; i++) {
        int row = m0 + (ty<<3) + i;
        float* orow = g_logits + (size_t)row * VOCAB + n0 + (tx<<3);
        *reinterpret_cast<float4*>(orow) =
            make_float4(acc[i][0]+bb[0], acc[i][1]+bb[1], acc[i][2]+bb[2], acc[i][3]+bb[3]);
        *reinterpret_cast<float4*>(orow + 4) =
            make_float4(acc[i][4]+bb[4], acc[i][5]+bb[5], acc[i][6]+bb[6], acc[i][7]+bb[7]);
    }
}

// ---------------------------------------------------------------------------
// Online log-softmax per row.
// ---------------------------------------------------------------------------
__global__ __launch_bounds__(256) void kSoftmax(float* __restrict__ out) {
    const int r = blockIdx.x;
    const float* __restrict__ row = g_logits + (size_t)r * VOCAB;
    float m = -INFINITY, s = 0.f;
    for (int v = threadIdx.x; v < VOCAB; v += 256) {
        float x = row[v];
        if (x > m) { s = s * expf(m - x) + 1.f; m = x; }
        else       { s += expf(x - m); }
    }
    __shared__ float sm[256], ss[256];
    sm[threadIdx.x] = m; ss[threadIdx.x] = s;
    __syncthreads();
    for (int st = 128; st > 0; st >>= 1) {
        if (threadIdx.x < st) {
            float m2 = sm[threadIdx.x + st], s2 = ss[threadIdx.x + st];
            float m1 = sm[threadIdx.x],      s1 = ss[threadIdx.x];
            float M = fmaxf(m1, m2);
            sm[threadIdx.x] = M;
            ss[threadIdx.x] = s1 * expf(m1 - M) + s2 * expf(m2 - M);
        }
        __syncthreads();
    }
    const float lse = sm[0] + logf(ss[0]);
    float* __restrict__ orow = out + (size_t)r * VOCAB;
    for (int v = threadIdx.x; v < VOCAB; v += 256)
        orow[v] = row[v] - lse;
}

// ---------------------------------------------------------------------------
// Launch
// ---------------------------------------------------------------------------
extern "C" void kernel_launch(void* const* d_in, const int* in_sizes, int n_in,
                              void* d_out, int out_size) {
    const int*   ids  = (const int*)  d_in[0];   // [64,32]
    const float* h0   = (const float*)d_in[1];   // [1,32,512]
    const float* emb  = (const float*)d_in[2];   // [32000,512]
    const float* W0   = (const float*)d_in[3];   // [1024,1024]
    const float* Ws   = (const float*)d_in[4];   // [8,8,512,1024]
    const float* bias = (const float*)d_in[5];   // [32000]
    float* out = (float*)d_out;                  // [64,32,32000] ++ [1,32,512]

    kInitH<<<64, 256>>>(h0);
    kEmbed<<<RROWS, 128>>>(ids, emb);
    kXpreGemm<<<dim3(NH2/64, RROWS/64), 256>>>(W0);
    kTransAll<<<dim3(32, 16, 29), 256>>>(W0, Ws);

    kRecur<<<NBLK, 256>>>(out + (size_t)RROWS * VOCAB);

    kDec2<<<dim3(VOCAB/128, RROWS/128), 256>>>(emb, bias);
    kSoftmax<<<RROWS, 256>>>(out);
}

// round 13
// speedup vs baseline: 1.4609x; 1.4609x over previous
#include <cuda_runtime.h>
#include <math.h>

#define TSTEPS 64
#define BATCH  32
#define NH     512
#define NH2    1024
#define VOCAB  32000
#define RROWS  (TSTEPS*BATCH)   // 2048
#define SELEM  (BATCH*NH)       // 16384
#define SMEM_BYTES (SELEM*4)    // 65536

// ---------------------------------------------------------------------------
// Scratch (static device globals; no allocation anywhere)
// ---------------------------------------------------------------------------
__device__ __align__(16) float g_X[RROWS*NH];
__device__ __align__(16) float g_Xpre[RROWS*NH2];
__device__ __align__(16) float g_states[8][SELEM];
__device__ __align__(16) float g_hid[RROWS*NH];
__device__ __align__(16) float g_logits[(size_t)RROWS*VOCAB];

__device__ __forceinline__ float sigm(float x) { return 1.f / (1.f + expf(-x)); }

// ---------------------------------------------------------------------------
// Embedding gather: one block per (t,b) row
// ---------------------------------------------------------------------------
__global__ __launch_bounds__(128) void kEmbed(const int* __restrict__ ids,
                                              const float* __restrict__ emb) {
    int r = blockIdx.x;
    int row = ids[r];
    const float4* src = reinterpret_cast<const float4*>(emb + (size_t)row * NH);
    float4* dst = reinterpret_cast<float4*>(g_X + (size_t)r * NH);
    dst[threadIdx.x] = src[threadIdx.x];
}

// ---------------------------------------------------------------------------
// Xpre = g_X[2048,512] @ W0[0:512, 0:1024]  (64x64 tile, 4x4 micro)
// ---------------------------------------------------------------------------
__global__ __launch_bounds__(256) void kXpreGemm(const float* __restrict__ W0) {
    __shared__ __align__(16) float As[16][64];
    __shared__ __align__(16) float Bs[16][64];
    const int m0 = blockIdx.y * 64, n0 = blockIdx.x * 64;
    const int tid = threadIdx.x, tx = tid & 15, ty = tid >> 4;
    const int am = tid >> 2, ak4 = (tid & 3) * 4;
    const int bk = tid >> 4, bn4 = (tid & 15) * 4;
    float acc[4][4];
#pragma unroll
    for (int i = 0; i < 4; i++)
#pragma unroll
        for (int j = 0; j < 4; j++) acc[i][j] = 0.f;
    for (int k0 = 0; k0 < NH; k0 += 16) {
        float4 av = *reinterpret_cast<const float4*>(g_X + (size_t)(m0+am)*NH + k0 + ak4);
        As[ak4+0][am] = av.x; As[ak4+1][am] = av.y; As[ak4+2][am] = av.z; As[ak4+3][am] = av.w;
        *reinterpret_cast<float4*>(&Bs[bk][bn4]) =
            *reinterpret_cast<const float4*>(W0 + (size_t)(k0+bk)*NH2 + n0 + bn4);
        __syncthreads();
#pragma unroll
        for (int kk = 0; kk < 16; kk++) {
            float4 a = *reinterpret_cast<float4*>(&As[kk][ty*4]);
            float4 b = *reinterpret_cast<float4*>(&Bs[kk][tx*4]);
            float aa[4] = {a.x,a.y,a.z,a.w}, bb[4] = {b.x,b.y,b.z,b.w};
#pragma unroll
            for (int i = 0; i < 4; i++)
#pragma unroll
                for (int j = 0; j < 4; j++) acc[i][j] += aa[i]*bb[j];
        }
        __syncthreads();
    }
#pragma unroll
    for (int i = 0; i < 4; i++) {
        float4 st = make_float4(acc[i][0], acc[i][1], acc[i][2], acc[i][3]);
        *reinterpret_cast<float4*>(g_Xpre + (size_t)(m0+ty*4+i)*NH2 + n0 + tx*4) = st;
    }
}

// ---------------------------------------------------------------------------
// Stage GEMM core shared by node0/edge kernels:
//   smem holds full (scaled) state [32][512]; lane<16 computes c-cols,
//   lane>=16 computes h-cols; warp w handles batches 4w..4w+3.
// Returns 4 accumulators (one per batch) for this thread's column.
// ---------------------------------------------------------------------------
__device__ __forceinline__ void stage_gemm(const float* __restrict__ Wcol,  // &W[0][col], row stride NH2
                                           const float* __restrict__ s_sm,
                                           int b0,
                                           float& a0, float& a1, float& a2, float& a3) {
    a0 = a1 = a2 = a3 = 0.f;
    const float4* s0p = reinterpret_cast<const float4*>(s_sm + (b0+0)*NH);
    const float4* s1p = reinterpret_cast<const float4*>(s_sm + (b0+1)*NH);
    const float4* s2p = reinterpret_cast<const float4*>(s_sm + (b0+2)*NH);
    const float4* s3p = reinterpret_cast<const float4*>(s_sm + (b0+3)*NH);
#pragma unroll 4
    for (int k4 = 0; k4 < 128; k4++) {
        float w0 = __ldg(Wcol + (size_t)(4*k4+0)*NH2);
        float w1 = __ldg(Wcol + (size_t)(4*k4+1)*NH2);
        float w2 = __ldg(Wcol + (size_t)(4*k4+2)*NH2);
        float w3 = __ldg(Wcol + (size_t)(4*k4+3)*NH2);
        float4 sA = s0p[k4], sB = s1p[k4], sC = s2p[k4], sD = s3p[k4];
        a0 = fmaf(sA.x,w0,a0); a0 = fmaf(sA.y,w1,a0); a0 = fmaf(sA.z,w2,a0); a0 = fmaf(sA.w,w3,a0);
        a1 = fmaf(sB.x,w0,a1); a1 = fmaf(sB.y,w1,a1); a1 = fmaf(sB.z,w2,a1); a1 = fmaf(sB.w,w3,a1);
        a2 = fmaf(sC.x,w0,a2); a2 = fmaf(sC.y,w1,a2); a2 = fmaf(sC.z,w2,a2); a2 = fmaf(sC.w,w3,a2);
        a3 = fmaf(sD.x,w0,a3); a3 = fmaf(sD.y,w1,a3); a3 = fmaf(sD.z,w2,a3); a3 = fmaf(sD.w,w3,a3);
    }
}

// ---------------------------------------------------------------------------
// node0 (fused with avg of previous step):
//   h = (t==0) ? h0 : mean_{j=1..7}(states[j]/j)        [also writes g_hid[t-1]]
//   [c|hc] = Xpre[t] + h @ W0[512:,:] ;  s0 = h + sig(c)*(tanh(hc)-h)
// Grid: 32 blocks x 256 threads; block handles 16 col-pairs.
// ---------------------------------------------------------------------------
__global__ __launch_bounds__(256) void kNode0S(const float* __restrict__ W0,
                                               const float* __restrict__ h0in, int t) {
    extern __shared__ float s_sm[];
    const int d0 = blockIdx.x << 4;
    {
        float4* sm4 = reinterpret_cast<float4*>(s_sm);
        const int tid = threadIdx.x;
        if (t == 0) {
            const float4* H4 = reinterpret_cast<const float4*>(h0in);
#pragma unroll
            for (int r = 0; r < 16; r++) sm4[r*256 + tid] = H4[r*256 + tid];
        } else {
#pragma unroll
            for (int r = 0; r < 16; r++) {
                const int i4 = r*256 + tid;
                float4 a = make_float4(0.f, 0.f, 0.f, 0.f);
#pragma unroll
                for (int jj = 1; jj < 8; jj++) {
                    float4 v = reinterpret_cast<const float4*>(g_states[jj])[i4];
                    float w = 1.f / (float)jj;
                    a.x += v.x*w; a.y += v.y*w; a.z += v.z*w; a.w += v.w*w;
                }
                const float c7 = 1.f / 7.f;
                a.x *= c7; a.y *= c7; a.z *= c7; a.w *= c7;
                sm4[i4] = a;
                if (blockIdx.x == 0)
                    reinterpret_cast<float4*>(g_hid)[(size_t)(t-1)*(SELEM/4) + i4] = a;
            }
        }
    }
    __syncthreads();

    const int lane = threadIdx.x & 31, warp = threadIdx.x >> 5;
    const int b0 = warp << 2;
    const bool isC = (lane < 16);
    const int col = isC ? (d0 + lane) : (NH + d0 + (lane - 16));
    const float* Wcol = W0 + (size_t)NH * NH2 + col;   // rows 512..1023

    float a0, a1, a2, a3;
    stage_gemm(Wcol, s_sm, b0, a0, a1, a2, a3);

    float h0v = __shfl_down_sync(0xffffffffu, a0, 16);
    float h1v = __shfl_down_sync(0xffffffffu, a1, 16);
    float h2v = __shfl_down_sync(0xffffffffu, a2, 16);
    float h3v = __shfl_down_sync(0xffffffffu, a3, 16);
    if (isC) {
        const int d = d0 + lane;
        const float* xp = g_Xpre + ((size_t)t * BATCH) * NH2;
        float cA[4] = {a0, a1, a2, a3};
        float hA[4] = {h0v, h1v, h2v, h3v};
#pragma unroll
        for (int q = 0; q < 4; q++) {
            const int b = b0 + q;
            float cc = cA[q] + xp[b*NH2 + d];
            float hh = hA[q] + xp[b*NH2 + NH + d];
            float hp = s_sm[b*NH + d];
            g_states[0][b*NH + d] = hp + sigm(cc) * (tanhf(hh) - hp);
        }
    }
}

// ---------------------------------------------------------------------------
// Edge stage i: for each j>i (blockIdx.y): [c|h] = (states[i]/cnt_i) @ Ws[i,j];
//   s = sp + sig(c)*(act_j(h) - sp);  states[j] = s (i==0) or += s (i>0)
// Grid: (32, 7-i) x 256 threads.
// ---------------------------------------------------------------------------
__global__ __launch_bounds__(256) void kEdgeS(const float* __restrict__ Ws, int i) {
    extern __shared__ float s_sm[];
    const int j  = i + 1 + blockIdx.y;
    const int d0 = blockIdx.x << 4;
    const float inv = (i == 0) ? 1.f : 1.f / (float)i;
    const float* __restrict__ S = g_states[i];
    const float* __restrict__ W = Ws + ((size_t)(i*8 + j) << 19);  // *512*1024
    {
        const float4* S4 = reinterpret_cast<const float4*>(S);
        float4* sm4 = reinterpret_cast<float4*>(s_sm);
        const int tid = threadIdx.x;
#pragma unroll
        for (int r = 0; r < 16; r++) {
            float4 v = S4[r*256 + tid];
            v.x *= inv; v.y *= inv; v.z *= inv; v.w *= inv;
            sm4[r*256 + tid] = v;
        }
    }
    __syncthreads();

    const int lane = threadIdx.x & 31, warp = threadIdx.x >> 5;
    const int b0 = warp << 2;
    const bool isC = (lane < 16);
    const int col = isC ? (d0 + lane) : (NH + d0 + (lane - 16));

    float a0, a1, a2, a3;
    stage_gemm(W + col, s_sm, b0, a0, a1, a2, a3);

    float h0v = __shfl_down_sync(0xffffffffu, a0, 16);
    float h1v = __shfl_down_sync(0xffffffffu, a1, 16);
    float h2v = __shfl_down_sync(0xffffffffu, a2, 16);
    float h3v = __shfl_down_sync(0xffffffffu, a3, 16);
    if (isC) {
        const int d = d0 + lane;
        float cA[4] = {a0, a1, a2, a3};
        float hA[4] = {h0v, h1v, h2v, h3v};
#pragma unroll
        for (int q = 0; q < 4; q++) {
            const int b = b0 + q;
            float sp = s_sm[b*NH + d];       // already scaled by inv
            float hh = hA[q];
            float act;
            if (j == 1 || j == 4)      act = tanhf(hh);
            else if (j == 2 || j == 5) act = fmaxf(hh, 0.f);
            else if (j == 3 || j == 6) act = sigm(hh);
            else                       act = hh;   // j == 7 identity
            float s = sp + sigm(cA[q]) * (act - sp);
            float* dst = &g_states[j][b*NH + d];
            if (i == 0) *dst = s;
            else        *dst = *dst + s;
        }
    }
}

// ---------------------------------------------------------------------------
// Final avg: h(T-1) -> g_hid[63] and last_h output
// ---------------------------------------------------------------------------
__global__ __launch_bounds__(256) void kAvgFinal(float* __restrict__ lastOut) {
    int idx = blockIdx.x * 256 + threadIdx.x;
    if (idx >= SELEM) return;
    float s = 0.f;
#pragma unroll
    for (int jj = 1; jj < 8; jj++) s += g_states[jj][idx] * (1.f / (float)jj);
    s *= (1.f / 7.f);
    g_hid[(size_t)(TSTEPS-1) * SELEM + idx] = s;
    lastOut[idx] = s;
}

// ---------------------------------------------------------------------------
// Decoder: logits[r,v] = g_hid[r,:] . emb[v,:] + bias[v]  (128x128, 8x8 micro)
// ---------------------------------------------------------------------------
__global__ __launch_bounds__(256) void kDec2(const float* __restrict__ emb,
                                             const float* __restrict__ bias) {
    __shared__ __align__(16) float As[16][132];
    __shared__ __align__(16) float Bs[16][132];
    const int m0 = blockIdx.y << 7, n0 = blockIdx.x << 7;
    const int tid = threadIdx.x;
    const int tx = tid & 15, ty = tid >> 4;
    const int lr = tid >> 1, lk = (tid & 1) << 3;
    float acc[8][8];
#pragma unroll
    for (int i = 0; i < 8; i++)
#pragma unroll
        for (int j = 0; j < 8; j++) acc[i][j] = 0.f;
    const float* Ap = g_hid + (size_t)(m0 + lr) * NH + lk;
    const float* Bp = emb   + (size_t)(n0 + lr) * NH + lk;

    for (int k0 = 0; k0 < NH; k0 += 16) {
        float4 a0 = __ldg(reinterpret_cast<const float4*>(Ap + k0));
        float4 a1 = __ldg(reinterpret_cast<const float4*>(Ap + k0 + 4));
        float4 b0 = __ldg(reinterpret_cast<const float4*>(Bp + k0));
        float4 b1 = __ldg(reinterpret_cast<const float4*>(Bp + k0 + 4));
        As[lk+0][lr]=a0.x; As[lk+1][lr]=a0.y; As[lk+2][lr]=a0.z; As[lk+3][lr]=a0.w;
        As[lk+4][lr]=a1.x; As[lk+5][lr]=a1.y; As[lk+6][lr]=a1.z; As[lk+7][lr]=a1.w;
        Bs[lk+0][lr]=b0.x; Bs[lk+1][lr]=b0.y; Bs[lk+2][lr]=b0.z; Bs[lk+3][lr]=b0.w;
        Bs[lk+4][lr]=b1.x; Bs[lk+5][lr]=b1.y; Bs[lk+6][lr]=b1.z; Bs[lk+7][lr]=b1.w;
        __syncthreads();
#pragma unroll
        for (int kk = 0; kk < 16; kk++) {
            float4 t0 = *reinterpret_cast<const float4*>(&As[kk][ty<<3]);
            float4 t1 = *reinterpret_cast<const float4*>(&As[kk][(ty<<3)+4]);
            float4 u0 = *reinterpret_cast<const float4*>(&Bs[kk][tx<<3]);
            float4 u1 = *reinterpret_cast<const float4*>(&Bs[kk][(tx<<3)+4]);
            float a[8] = {t0.x,t0.y,t0.z,t0.w,t1.x,t1.y,t1.z,t1.w};
            float b[8] = {u0.x,u0.y,u0.z,u0.w,u1.x,u1.y,u1.z,u1.w};
#pragma unroll
            for (int i = 0; i < 8; i++)
#pragma unroll
                for (int j = 0; j < 8; j++) acc[i][j] = fmaf(a[i], b[j], acc[i][j]);
        }
        __syncthreads();
    }
    float4 bz0 = __ldg(reinterpret_cast<const float4*>(bias + n0 + (tx<<3)));
    float4 bz1 = __ldg(reinterpret_cast<const float4*>(bias + n0 + (tx<<3) + 4));
    float bb[8] = {bz0.x,bz0.y,bz0.z,bz0.w,bz1.x,bz1.y,bz1.z,bz1.w};
#pragma unroll
    for (int i = 0; i < 8; i++) {
        int row = m0 + (ty<<3) + i;
        float* orow = g_logits + (size_t)row * VOCAB + n0 + (tx<<3);
        *reinterpret_cast<float4*>(orow) =
            make_float4(acc[i][0]+bb[0], acc[i][1]+bb[1], acc[i][2]+bb[2], acc[i][3]+bb[3]);
        *reinterpret_cast<float4*>(orow + 4) =
            make_float4(acc[i][4]+bb[4], acc[i][5]+bb[5], acc[i][6]+bb[6], acc[i][7]+bb[7]);
    }
}

// ---------------------------------------------------------------------------
// Online log-softmax per row
// ---------------------------------------------------------------------------
__global__ __launch_bounds__(256) void kSoftmax(float* __restrict__ out) {
    const int r = blockIdx.x;
    const float* __restrict__ row = g_logits + (size_t)r * VOCAB;
    float m = -INFINITY, s = 0.f;
    for (int v = threadIdx.x; v < VOCAB; v += 256) {
        float x = row[v];
        if (x > m) { s = s * expf(m - x) + 1.f; m = x; }
        else       { s += expf(x - m); }
    }
    __shared__ float sm[256], ss[256];
    sm[threadIdx.x] = m; ss[threadIdx.x] = s;
    __syncthreads();
    for (int st = 128; st > 0; st >>= 1) {
        if (threadIdx.x < st) {
            float m2 = sm[threadIdx.x + st], s2 = ss[threadIdx.x + st];
            float m1 = sm[threadIdx.x],      s1 = ss[threadIdx.x];
            float M = fmaxf(m1, m2);
            sm[threadIdx.x] = M;
            ss[threadIdx.x] = s1 * expf(m1 - M) + s2 * expf(m2 - M);
        }
        __syncthreads();
    }
    const float lse = sm[0] + logf(ss[0]);
    float* __restrict__ orow = out + (size_t)r * VOCAB;
    for (int v = threadIdx.x; v < VOCAB; v += 256)
        orow[v] = row[v] - lse;
}

// ---------------------------------------------------------------------------
// Launch
// ---------------------------------------------------------------------------
extern "C" void kernel_launch(void* const* d_in, const int* in_sizes, int n_in,
                              void* d_out, int out_size) {
    const int*   ids  = (const int*)  d_in[0];   // [64,32]
    const float* h0   = (const float*)d_in[1];   // [1,32,512]
    const float* emb  = (const float*)d_in[2];   // [32000,512]
    const float* W0   = (const float*)d_in[3];   // [1024,1024]
    const float* Ws   = (const float*)d_in[4];   // [8,8,512,1024]
    const float* bias = (const float*)d_in[5];   // [32000]
    float* out = (float*)d_out;                  // [64,32,32000] ++ [1,32,512]

    cudaFuncSetAttribute(kNode0S, cudaFuncAttributeMaxDynamicSharedMemorySize, SMEM_BYTES);
    cudaFuncSetAttribute(kEdgeS,  cudaFuncAttributeMaxDynamicSharedMemorySize, SMEM_BYTES);

    kEmbed<<<RROWS, 128>>>(ids, emb);
    kXpreGemm<<<dim3(NH2/64, RROWS/64), 256>>>(W0);

    for (int t = 0; t < TSTEPS; t++) {
        kNode0S<<<32, 256, SMEM_BYTES>>>(W0, h0, t);
        for (int i = 0; i < 7; i++)
            kEdgeS<<<dim3(32, 7 - i), 256, SMEM_BYTES>>>(Ws, i);
    }
    kAvgFinal<<<64, 256>>>(out + (size_t)RROWS * VOCAB);

    kDec2<<<dim3(VOCAB/128, RROWS/128), 256>>>(emb, bias);
    kSoftmax<<<RROWS, 256>>>(out);
}

// round 14
// speedup vs baseline: 2.5727x; 1.7611x over previous
#include <cuda_runtime.h>
#include <math.h>

#define TSTEPS 64
#define BATCH  32
#define NH     512
#define NH2    1024
#define VOCAB  32000
#define RROWS  (TSTEPS*BATCH)   // 2048
#define SELEM  (BATCH*NH)       // 16384
#define STG_SMEM ((NH*32 + 32*32)*4)   // 69632 bytes

// ---------------------------------------------------------------------------
// Scratch (static device globals; no allocation anywhere)
// ---------------------------------------------------------------------------
__device__ __align__(16) float g_X[RROWS*NH];
__device__ __align__(16) float g_Xpre[RROWS*NH2];
__device__ __align__(16) float g_statesT[8][SELEM];   // transposed [d][b]
__device__ __align__(16) float g_hidT[RROWS*NH];      // [t][d][b]
__device__ __align__(16) float g_logits[(size_t)RROWS*VOCAB];

__device__ __forceinline__ float sigm(float x) { return 1.f / (1.f + expf(-x)); }

// ---------------------------------------------------------------------------
// Embedding gather
// ---------------------------------------------------------------------------
__global__ __launch_bounds__(128) void kEmbed(const int* __restrict__ ids,
                                              const float* __restrict__ emb) {
    int r = blockIdx.x;
    int row = ids[r];
    const float4* src = reinterpret_cast<const float4*>(emb + (size_t)row * NH);
    float4* dst = reinterpret_cast<float4*>(g_X + (size_t)r * NH);
    dst[threadIdx.x] = src[threadIdx.x];
}

// ---------------------------------------------------------------------------
// Xpre = g_X[2048,512] @ W0[0:512, 0:1024]  (64x64 tile, 4x4 micro)
// ---------------------------------------------------------------------------
__global__ __launch_bounds__(256) void kXpreGemm(const float* __restrict__ W0) {
    __shared__ __align__(16) float As[16][64];
    __shared__ __align__(16) float Bs[16][64];
    const int m0 = blockIdx.y * 64, n0 = blockIdx.x * 64;
    const int tid = threadIdx.x, tx = tid & 15, ty = tid >> 4;
    const int am = tid >> 2, ak4 = (tid & 3) * 4;
    const int bk = tid >> 4, bn4 = (tid & 15) * 4;
    float acc[4][4];
#pragma unroll
    for (int i = 0; i < 4; i++)
#pragma unroll
        for (int j = 0; j < 4; j++) acc[i][j] = 0.f;
    for (int k0 = 0; k0 < NH; k0 += 16) {
        float4 av = *reinterpret_cast<const float4*>(g_X + (size_t)(m0+am)*NH + k0 + ak4);
        As[ak4+0][am] = av.x; As[ak4+1][am] = av.y; As[ak4+2][am] = av.z; As[ak4+3][am] = av.w;
        *reinterpret_cast<float4*>(&Bs[bk][bn4]) =
            *reinterpret_cast<const float4*>(W0 + (size_t)(k0+bk)*NH2 + n0 + bn4);
        __syncthreads();
#pragma unroll
        for (int kk = 0; kk < 16; kk++) {
            float4 a = *reinterpret_cast<float4*>(&As[kk][ty*4]);
            float4 b = *reinterpret_cast<float4*>(&Bs[kk][tx*4]);
            float aa[4] = {a.x,a.y,a.z,a.w}, bb[4] = {b.x,b.y,b.z,b.w};
#pragma unroll
            for (int i = 0; i < 4; i++)
#pragma unroll
                for (int j = 0; j < 4; j++) acc[i][j] += aa[i]*bb[j];
        }
        __syncthreads();
    }
#pragma unroll
    for (int i = 0; i < 4; i++) {
        float4 st = make_float4(acc[i][0], acc[i][1], acc[i][2], acc[i][3]);
        *reinterpret_cast<float4*>(g_Xpre + (size_t)(m0+ty*4+i)*NH2 + n0 + tx*4) = st;
    }
}

// ---------------------------------------------------------------------------
// Unified stage kernel.
//   i == -1 : node0. A = h (t==0: h0in; else avg of states/j/7, also writes
//             g_hidT[t-1]).  W = W0 rows 512..1023.  Epilogue uses Xpre.
//   i >= 0  : edge stage. A = states[i]/cnt_i. j = i+1+blockIdx.y.
// Tile: 32 batch x 16 (c,h) column pairs. 128 threads, full-K A in smem.
// ---------------------------------------------------------------------------
__global__ __launch_bounds__(128, 2) void kStage(const float* __restrict__ Wbase,
                                                 const float* __restrict__ h0in,
                                                 int i, int t) {
    extern __shared__ float smem[];
    float* As = smem;               // [512][32]  ([k][b])
    float* Bs = smem + NH * 32;     // [32][32]   (c cols 0..15 | h cols 16..31)
    const int tid = threadIdx.x;
    const int d0 = blockIdx.x << 4;

    // ---- prologue: stage A into As[k][b] (coalesced float4 copy)
    if (i >= 0) {
        const float inv = (i == 0) ? 1.f : 1.f / (float)i;
        const float4* S4 = reinterpret_cast<const float4*>(g_statesT[i]);
        float4* A4 = reinterpret_cast<float4*>(As);
#pragma unroll 4
        for (int w = 0; w < 32; w++) {
            float4 v = S4[w*128 + tid];
            v.x *= inv; v.y *= inv; v.z *= inv; v.w *= inv;
            A4[w*128 + tid] = v;
        }
    } else if (t > 0) {
        float4* A4 = reinterpret_cast<float4*>(As);
        float4* H4 = reinterpret_cast<float4*>(g_hidT + (size_t)(t-1)*SELEM);
        const bool wr = (blockIdx.x == 0);
#pragma unroll 2
        for (int w = 0; w < 32; w++) {
            float4 a = make_float4(0.f, 0.f, 0.f, 0.f);
#pragma unroll
            for (int jj = 1; jj < 8; jj++) {
                float4 v = reinterpret_cast<const float4*>(g_statesT[jj])[w*128 + tid];
                float wg = 1.f / (float)jj;
                a.x += v.x*wg; a.y += v.y*wg; a.z += v.z*wg; a.w += v.w*wg;
            }
            const float c7 = 1.f / 7.f;
            a.x *= c7; a.y *= c7; a.z *= c7; a.w *= c7;
            A4[w*128 + tid] = a;
            if (wr) H4[w*128 + tid] = a;
        }
    } else {
        // t == 0: transpose h0in [b][d] -> As[d][b]
        const int b = tid & 31, kg = (tid >> 5) << 3;
        for (int kb = 0; kb < NH; kb += 32) {
            const int k = kb + kg;
            float4 p0 = *reinterpret_cast<const float4*>(h0in + b*NH + k);
            float4 p1 = *reinterpret_cast<const float4*>(h0in + b*NH + k + 4);
            As[(k+0)*32+b]=p0.x; As[(k+1)*32+b]=p0.y; As[(k+2)*32+b]=p0.z; As[(k+3)*32+b]=p0.w;
            As[(k+4)*32+b]=p1.x; As[(k+5)*32+b]=p1.y; As[(k+6)*32+b]=p1.z; As[(k+7)*32+b]=p1.w;
        }
    }

    int j = 0;
    const float* W;
    if (i < 0) { W = Wbase; }
    else { j = i + 1 + blockIdx.y; W = Wbase + ((size_t)(i*8 + j) << 19); }

    __syncthreads();

    const int tx = tid & 15, ty = tid >> 4;   // tx: pair col; ty: batch group
    const int b0 = ty << 2;
    const int r  = tid >> 2, f4 = (tid & 3) << 2;
    float cA[4] = {0,0,0,0}, hA[4] = {0,0,0,0};

    // prefetch first B chunk
    const float* wr0 = W + (size_t)r * NH2 + d0;
    float4 pc = __ldg(reinterpret_cast<const float4*>(wr0 + f4));
    float4 ph = __ldg(reinterpret_cast<const float4*>(wr0 + NH + f4));

    for (int k0 = 0; k0 < NH; k0 += 32) {
        *reinterpret_cast<float4*>(Bs + r*32 + f4)      = pc;
        *reinterpret_cast<float4*>(Bs + r*32 + 16 + f4) = ph;
        __syncthreads();
        if (k0 + 32 < NH) {
            const float* wrn = W + (size_t)(k0 + 32 + r) * NH2 + d0;
            pc = __ldg(reinterpret_cast<const float4*>(wrn + f4));
            ph = __ldg(reinterpret_cast<const float4*>(wrn + NH + f4));
        }
#pragma unroll 8
        for (int kk = 0; kk < 32; kk++) {
            float4 a = *reinterpret_cast<const float4*>(As + (k0+kk)*32 + b0);
            float bc = Bs[kk*32 + tx];
            float bh = Bs[kk*32 + 16 + tx];
            cA[0] = fmaf(a.x, bc, cA[0]); hA[0] = fmaf(a.x, bh, hA[0]);
            cA[1] = fmaf(a.y, bc, cA[1]); hA[1] = fmaf(a.y, bh, hA[1]);
            cA[2] = fmaf(a.z, bc, cA[2]); hA[2] = fmaf(a.z, bh, hA[2]);
            cA[3] = fmaf(a.w, bc, cA[3]); hA[3] = fmaf(a.w, bh, hA[3]);
        }
        __syncthreads();
    }

    const int d = d0 + tx;
    if (i < 0) {
        const float* xp = g_Xpre + ((size_t)t * BATCH) * NH2;
        float s[4];
#pragma unroll
        for (int q = 0; q < 4; q++) {
            const int b = b0 + q;
            float cc = cA[q] + __ldg(xp + b*NH2 + d);
            float hh = hA[q] + __ldg(xp + b*NH2 + NH + d);
            float hp = As[d*32 + b];
            s[q] = hp + sigm(cc) * (tanhf(hh) - hp);
        }
        *reinterpret_cast<float4*>(g_statesT[0] + d*32 + b0) =
            make_float4(s[0], s[1], s[2], s[3]);
    } else {
        float s[4];
#pragma unroll
        for (int q = 0; q < 4; q++) {
            const int b = b0 + q;
            float sp = As[d*32 + b];         // already scaled by inv
            float hh = hA[q];
            float act;
            if (j == 1 || j == 4)      act = tanhf(hh);
            else if (j == 2 || j == 5) act = fmaxf(hh, 0.f);
            else if (j == 3 || j == 6) act = sigm(hh);
            else                       act = hh;    // j == 7 identity
            s[q] = sp + sigm(cA[q]) * (act - sp);
        }
        float4* dst = reinterpret_cast<float4*>(g_statesT[j] + d*32 + b0);
        if (i == 0) *dst = make_float4(s[0], s[1], s[2], s[3]);
        else {
            float4 o = *dst;
            *dst = make_float4(o.x+s[0], o.y+s[1], o.z+s[2], o.w+s[3]);
        }
    }
}

// ---------------------------------------------------------------------------
// Final avg: write g_hidT[63] and last_h output (row-major [b][d])
// ---------------------------------------------------------------------------
__global__ __launch_bounds__(256) void kAvgFinal(float* __restrict__ lastOut) {
    int idx = blockIdx.x * 256 + threadIdx.x;   // = d*32 + b
    float s = 0.f;
#pragma unroll
    for (int jj = 1; jj < 8; jj++) s += g_statesT[jj][idx] * (1.f / (float)jj);
    s *= (1.f / 7.f);
    g_hidT[(size_t)(TSTEPS-1) * SELEM + idx] = s;
    int d = idx >> 5, b = idx & 31;
    lastOut[b * NH + d] = s;
}

// ---------------------------------------------------------------------------
// Decoder: logits[r,v] = hid[r,:] . emb[v,:] + bias[v]  (128x128, 8x8 micro)
// A read from transposed g_hidT [t][k][b]; rows r = t*32+b.
// ---------------------------------------------------------------------------
__global__ __launch_bounds__(256) void kDec2(const float* __restrict__ emb,
                                             const float* __restrict__ bias) {
    __shared__ __align__(16) float As[16][132];
    __shared__ __align__(16) float Bs[16][132];
    const int m0 = blockIdx.y << 7, n0 = blockIdx.x << 7;
    const int tRow0 = m0 >> 5;                 // 4 consecutive t indices
    const int tid = threadIdx.x;
    const int tx = tid & 15, ty = tid >> 4;
    const int lr = tid >> 1, lk = (tid & 1) << 3;
    float acc[8][8];
#pragma unroll
    for (int i = 0; i < 8; i++)
#pragma unroll
        for (int j = 0; j < 8; j++) acc[i][j] = 0.f;
    const float* Bp = emb + (size_t)(n0 + lr) * NH + lk;

    for (int k0 = 0; k0 < NH; k0 += 16) {
        // A: 512 float4 slots; slot -> (tg, kk, b4)
        {
            int s2 = tid;
#pragma unroll
            for (int rep = 0; rep < 2; rep++) {
                int tg = s2 >> 7, kk = (s2 >> 3) & 15, b4 = (s2 & 7) << 2;
                float4 v = *reinterpret_cast<const float4*>(
                    g_hidT + (size_t)(tRow0 + tg)*SELEM + (k0+kk)*32 + b4);
                *reinterpret_cast<float4*>(&As[kk][tg*32 + b4]) = v;
                s2 += 256;
            }
        }
        float4 b0v = __ldg(reinterpret_cast<const float4*>(Bp + k0));
        float4 b1v = __ldg(reinterpret_cast<const float4*>(Bp + k0 + 4));
        Bs[lk+0][lr]=b0v.x; Bs[lk+1][lr]=b0v.y; Bs[lk+2][lr]=b0v.z; Bs[lk+3][lr]=b0v.w;
        Bs[lk+4][lr]=b1v.x; Bs[lk+5][lr]=b1v.y; Bs[lk+6][lr]=b1v.z; Bs[lk+7][lr]=b1v.w;
        __syncthreads();
#pragma unroll
        for (int kk = 0; kk < 16; kk++) {
            float4 t0 = *reinterpret_cast<const float4*>(&As[kk][ty<<3]);
            float4 t1 = *reinterpret_cast<const float4*>(&As[kk][(ty<<3)+4]);
            float4 u0 = *reinterpret_cast<const float4*>(&Bs[kk][tx<<3]);
            float4 u1 = *reinterpret_cast<const float4*>(&Bs[kk][(tx<<3)+4]);
            float a[8] = {t0.x,t0.y,t0.z,t0.w,t1.x,t1.y,t1.z,t1.w};
            float b[8] = {u0.x,u0.y,u0.z,u0.w,u1.x,u1.y,u1.z,u1.w};
#pragma unroll
            for (int i = 0; i < 8; i++)
#pragma unroll
                for (int j = 0; j < 8; j++) acc[i][j] = fmaf(a[i], b[j], acc[i][j]);
        }
        __syncthreads();
    }
    float4 bz0 = __ldg(reinterpret_cast<const float4*>(bias + n0 + (tx<<3)));
    float4 bz1 = __ldg(reinterpret_cast<const float4*>(bias + n0 + (tx<<3) + 4));
    float bb[8] = {bz0.x,bz0.y,bz0.z,bz0.w,bz1.x,bz1.y,bz1.z,bz1.w};
#pragma unroll
    for (int i = 0; i < 8; i++) {
        int row = m0 + (ty<<3) + i;
        float* orow = g_logits + (size_t)row * VOCAB + n0 + (tx<<3);
        *reinterpret_cast<float4*>(orow) =
            make_float4(acc[i][0]+bb[0], acc[i][1]+bb[1], acc[i][2]+bb[2], acc[i][3]+bb[3]);
        *reinterpret_cast<float4*>(orow + 4) =
            make_float4(acc[i][4]+bb[4], acc[i][5]+bb[5], acc[i][6]+bb[6], acc[i][7]+bb[7]);
    }
}

// ---------------------------------------------------------------------------
// Online log-softmax per row
// ---------------------------------------------------------------------------
__global__ __launch_bounds__(256) void kSoftmax(float* __restrict__ out) {
    const int r = blockIdx.x;
    const float* __restrict__ row = g_logits + (size_t)r * VOCAB;
    float m = -INFINITY, s = 0.f;
    for (int v = threadIdx.x; v < VOCAB; v += 256) {
        float x = row[v];
        if (x > m) { s = s * expf(m - x) + 1.f; m = x; }
        else       { s += expf(x - m); }
    }
    __shared__ float sm[256], ss[256];
    sm[threadIdx.x] = m; ss[threadIdx.x] = s;
    __syncthreads();
    for (int st = 128; st > 0; st >>= 1) {
        if (threadIdx.x < st) {
            float m2 = sm[threadIdx.x + st], s2 = ss[threadIdx.x + st];
            float m1 = sm[threadIdx.x],      s1 = ss[threadIdx.x];
            float M = fmaxf(m1, m2);
            sm[threadIdx.x] = M;
            ss[threadIdx.x] = s1 * expf(m1 - M) + s2 * expf(m2 - M);
        }
        __syncthreads();
    }
    const float lse = sm[0] + logf(ss[0]);
    float* __restrict__ orow = out + (size_t)r * VOCAB;
    for (int v = threadIdx.x; v < VOCAB; v += 256)
        orow[v] = row[v] - lse;
}

// ---------------------------------------------------------------------------
// Launch
// ---------------------------------------------------------------------------
extern "C" void kernel_launch(void* const* d_in, const int* in_sizes, int n_in,
                              void* d_out, int out_size) {
    const int*   ids  = (const int*)  d_in[0];   // [64,32]
    const float* h0   = (const float*)d_in[1];   // [1,32,512]
    const float* emb  = (const float*)d_in[2];   // [32000,512]
    const float* W0   = (const float*)d_in[3];   // [1024,1024]
    const float* Ws   = (const float*)d_in[4];   // [8,8,512,1024]
    const float* bias = (const float*)d_in[5];   // [32000]
    float* out = (float*)d_out;                  // [64,32,32000] ++ [1,32,512]

    cudaFuncSetAttribute(kStage, cudaFuncAttributeMaxDynamicSharedMemorySize, STG_SMEM);

    kEmbed<<<RROWS, 128>>>(ids, emb);
    kXpreGemm<<<dim3(NH2/64, RROWS/64), 256>>>(W0);

    const float* W0h = W0 + (size_t)NH * NH2;
    for (int t = 0; t < TSTEPS; t++) {
        kStage<<<dim3(32, 1), 128, STG_SMEM>>>(W0h, h0, -1, t);
        for (int i = 0; i < 7; i++)
            kStage<<<dim3(32, 7 - i), 128, STG_SMEM>>>(Ws, nullptr, i, t);
    }
    kAvgFinal<<<64, 256>>>(out + (size_t)RROWS * VOCAB);

    kDec2<<<dim3(VOCAB/128, RROWS/128), 256>>>(emb, bias);
    kSoftmax<<<RROWS, 256>>>(out);
}